// round 14
// baseline (speedup 1.0000x reference)
#include <cuda_runtime.h>
#include <cuda_bf16.h>
#include <stdint.h>
#include <math.h>

// Problem constants
#define BB 2
#define SS 2048
#define DD 1024
#define RR 64
#define HH 16
#define DH 64
#define NN 32
#define BS (BB*SS)        // 4096
#define NR (NN*RR)        // 2048

// ===================== PTX helpers (compute_103-safe) =====================
__device__ __forceinline__ uint32_t smem_u32(const void* p) {
    uint32_t a;
    asm("{ .reg .u64 t; cvta.to.shared.u64 t, %1; cvt.u32.u64 %0, t; }" : "=r"(a) : "l"(p));
    return a;
}
__device__ __forceinline__ void cp16(uint32_t saddr, const void* g) {
    asm volatile("cp.async.cg.shared.global [%0], [%1], 16;" :: "r"(saddr), "l"(g) : "memory");
}
#define CP_COMMIT() asm volatile("cp.async.commit_group;" ::: "memory")
#define CP_WAIT1()  asm volatile("cp.async.wait_group 1;" ::: "memory")
#define CP_WAIT0()  asm volatile("cp.async.wait_group 0;" ::: "memory")

#define LDSM4(r0, r1, r2, r3, addr) \
    asm volatile("ldmatrix.sync.aligned.m8n8.x4.shared.b16 {%0,%1,%2,%3}, [%4];" \
        : "=r"(r0), "=r"(r1), "=r"(r2), "=r"(r3) : "r"(addr))

#define MMA16816(d, a, b) \
    asm volatile("mma.sync.aligned.m16n8k16.row.col.f32.bf16.bf16.f32 " \
        "{%0,%1,%2,%3}, {%4,%5,%6,%7}, {%8,%9}, {%0,%1,%2,%3};" \
        : "+f"((d)[0]), "+f"((d)[1]), "+f"((d)[2]), "+f"((d)[3]) \
        : "r"((a)[0]), "r"((a)[1]), "r"((a)[2]), "r"((a)[3]), "r"((b)[0]), "r"((b)[1]))

// packed fp32 (Blackwell f32x2)
typedef unsigned long long u64t;
__device__ __forceinline__ u64t pack2(float lo, float hi) {
    u64t r; asm("mov.b64 %0, {%1,%2};" : "=l"(r) : "f"(lo), "f"(hi)); return r;
}
__device__ __forceinline__ void unpack2(u64t v, float& lo, float& hi) {
    asm("mov.b64 {%0,%1}, %2;" : "=f"(lo), "=f"(hi) : "l"(v));
}
__device__ __forceinline__ void fma2(u64t& d, u64t a, u64t b) {
    asm("fma.rn.f32x2 %0, %1, %2, %0;" : "+l"(d) : "l"(a), "l"(b));
}
__device__ __forceinline__ void mul2(u64t& d, u64t a) {
    asm("mul.rn.f32x2 %0, %0, %1;" : "+l"(d) : "l"(a));
}

// ===================== scratch (device globals) — COMPACT part layout =====================
__device__ __align__(256) __nv_bfloat16 g_Xp  [(size_t)BS * 3072];      // X  {h,m,l}
__device__ __align__(256) __nv_bfloat16 g_Fp  [(size_t)NR * 3072];      // f_qk^T {h,m,l}
__device__ __align__(256) __nv_bfloat16 g_Fvp [(size_t)NR * 2048];      // f_v^T {h,m}
__device__ __align__(256) __nv_bfloat16 g_HWp [(size_t)2 * BS * 6144];  // [Qb0|Kb0|Qb1|Kb1] {h,m,l}
__device__ __align__(256) __nv_bfloat16 g_HWv [(size_t)BS * 4096];      // HW v {h,m}
__device__ __align__(256) __nv_bfloat16 g_Rp  [(size_t)DD * 6144];      // r_qk^T {h,m,l}
__device__ __align__(256) __nv_bfloat16 g_Rvp [(size_t)DD * 4096];      // r_v^T {h,m}
__device__ __align__(256) __nv_bfloat16 g_WOp [(size_t)DD * 2048];      // W_O {h,m}
__device__ __align__(256) __nv_bfloat16 g_AOp [(size_t)BS * 2048];      // AO {h,m} (written by flash)
__device__ float g_P  [(size_t)BS * NR];      // proj-qk output
__device__ float g_P2 [(size_t)BS * NR];      // proj-v output
__device__ float g_hq [BS * RR];
__device__ float g_hk [BS * RR];
__device__ float g_hv [BS * RR];
__device__ float g_QK [(size_t)2 * BS * DD];  // [Qb0 | Kb0 | Qb1 | Kb1], 2048x1024 each
__device__ float g_V  [(size_t)BS * DD];

// ===================== split helpers =====================
__device__ __forceinline__ void split3f(float x, __nv_bfloat16& h, __nv_bfloat16& m, __nv_bfloat16& l) {
    h = __float2bfloat16_rn(x);
    float r = x - __bfloat162float(h);
    m = __float2bfloat16_rn(r);
    r -= __bfloat162float(m);
    l = __float2bfloat16_rn(r);
}
__device__ __forceinline__ void split2f(float x, __nv_bfloat16& h, __nv_bfloat16& m) {
    h = __float2bfloat16_rn(x);
    m = __float2bfloat16_rn(x - __bfloat162float(h));
}

__global__ void conv_x3(const float* __restrict__ in, __nv_bfloat16* __restrict__ out) {
    size_t gid = (size_t)blockIdx.x * 256 + threadIdx.x;  // BS*DD
    size_t row = gid >> 10; int col = (int)(gid & 1023);
    __nv_bfloat16 h, m, l; split3f(in[gid], h, m, l);
    __nv_bfloat16* o = out + row * 3072 + col;
    o[0] = h; o[1024] = m; o[2048] = l;
}

__global__ void conv_f3(const float* __restrict__ f, __nv_bfloat16* __restrict__ out) {
    size_t gid = (size_t)blockIdx.x * 256 + threadIdx.x;   // NR*DD
    int nr = (int)(gid >> 10), d = (int)(gid & 1023);
    int n = nr >> 6, r = nr & 63;
    __nv_bfloat16 h, m, l; split3f(f[((size_t)n << 16) + (d << 6) + r], h, m, l);
    __nv_bfloat16* o = out + (size_t)nr * 3072 + d;
    o[0] = h; o[1024] = m; o[2048] = l;
}
__global__ void conv_f2(const float* __restrict__ f, __nv_bfloat16* __restrict__ out) {
    size_t gid = (size_t)blockIdx.x * 256 + threadIdx.x;
    int nr = (int)(gid >> 10), d = (int)(gid & 1023);
    int n = nr >> 6, r = nr & 63;
    __nv_bfloat16 h, m, l; split3f(f[((size_t)n << 16) + (d << 6) + r], h, m, l);
    __nv_bfloat16* o = out + (size_t)nr * 2048 + d;
    o[0] = h; o[1024] = m;
}

__global__ void conv_r3(const float* __restrict__ rk, __nv_bfloat16* __restrict__ out) {
    size_t gid = (size_t)blockIdx.x * 256 + threadIdx.x;   // DD*NR
    int d = (int)(gid >> 11), nr = (int)(gid & 2047);
    int n = nr >> 6, r = nr & 63;
    __nv_bfloat16 h, m, l; split3f(rk[((size_t)n << 16) + (r << 10) + d], h, m, l);
    __nv_bfloat16* o = out + (size_t)d * 6144 + nr;
    o[0] = h; o[2048] = m; o[4096] = l;
}
__global__ void conv_r2(const float* __restrict__ rv, __nv_bfloat16* __restrict__ out) {
    size_t gid = (size_t)blockIdx.x * 256 + threadIdx.x;
    int d = (int)(gid >> 11), nr = (int)(gid & 2047);
    int n = nr >> 6, r = nr & 63;
    __nv_bfloat16 h, m, l; split3f(rv[((size_t)n << 16) + (r << 10) + d], h, m, l);
    __nv_bfloat16* o = out + (size_t)d * 4096 + nr;
    o[0] = h; o[2048] = m;
}

__global__ void conv_wo2(const float* __restrict__ w, __nv_bfloat16* __restrict__ out) {
    size_t gid = (size_t)blockIdx.x * 256 + threadIdx.x;  // DD*DD
    size_t row = gid >> 10; int col = (int)(gid & 1023);
    __nv_bfloat16 h, m, l; split3f(w[gid], h, m, l);
    __nv_bfloat16* o = out + row * 2048 + col;
    o[0] = h; o[1024] = m;
}

// HW {h,m,l} over 2048 rows (one batch, one of q/k): out[row][3*2048]
__global__ void build_hw3(const float* __restrict__ hbuf, const float* __restrict__ w,
                          __nv_bfloat16* __restrict__ out) {
    size_t gid = (size_t)blockIdx.x * 256 + threadIdx.x;   // 2048*NR
    int bs = (int)(gid >> 11), nr = (int)(gid & 2047);
    int n = nr >> 6, r = nr & 63;
    float p = hbuf[bs * RR + r] * w[bs * NN + n];
    __nv_bfloat16 h, m, l; split3f(p, h, m, l);
    __nv_bfloat16* o = out + (size_t)bs * 6144 + nr;
    o[0] = h; o[2048] = m; o[4096] = l;
}
__global__ void build_hw2(const float* __restrict__ hbuf, const float* __restrict__ w,
                          __nv_bfloat16* __restrict__ out) {
    size_t gid = (size_t)blockIdx.x * 256 + threadIdx.x;   // BS*NR
    int bs = (int)(gid >> 11), nr = (int)(gid & 2047);
    int n = nr >> 6, r = nr & 63;
    float p = hbuf[bs * RR + r] * w[bs * NN + n];
    __nv_bfloat16 h, m, l; split3f(p, h, m, l);
    __nv_bfloat16* o = out + (size_t)bs * 4096 + nr;
    o[0] = h; o[2048] = m;
}

// ===================== h reductions (P fp32) =====================
__global__ void reduce_h2(const float* __restrict__ P,
                          const float* __restrict__ wQ, const float* __restrict__ wK,
                          float* __restrict__ hq, float* __restrict__ hk) {
    int gid = blockIdx.x * 256 + threadIdx.x;   // BS*RR
    int bs = gid >> 6, r = gid & 63;
    const float* Pr = P + (size_t)bs * NR + r;
    const float* wq = wQ + bs * NN;
    const float* wk = wK + bs * NN;
    float aq = 0.f, ak = 0.f;
    #pragma unroll
    for (int n = 0; n < NN; n++) {
        float p = Pr[n * RR];
        aq += wq[n] * p;
        ak += wk[n] * p;
    }
    hq[gid] = aq; hk[gid] = ak;
}
__global__ void reduce_h1(const float* __restrict__ P, const float* __restrict__ w,
                          float* __restrict__ h) {
    int gid = blockIdx.x * 256 + threadIdx.x;
    int bs = gid >> 6, r = gid & 63;
    const float* Pr = P + (size_t)bs * NR + r;
    const float* ww = w + bs * NN;
    float a = 0.f;
    #pragma unroll
    for (int n = 0; n < NN; n++) a += ww[n] * Pr[n * RR];
    h[gid] = a;
}

// ===================== fused multi-part bf16 mma.sync GEMM (512 thr) =====================
template<int NT>
__global__ __launch_bounds__(512, 1)
void tgemm_p(const __nv_bfloat16* __restrict__ A, const __nv_bfloat16* __restrict__ B,
             float* __restrict__ C, int lda_i, int ldb_i, int ldc_i, int T)
{
    extern __shared__ char sm[];
    const uint32_t STAGE = NT * 32768u;
    uint32_t sbase = smem_u32(sm);
    int tid = threadIdx.x, wid = tid >> 5, lane = tid & 31;
    int warp_m = wid & 3, warp_n = wid >> 2;    // 4 x 4
    size_t lda = (size_t)lda_i, ldb = (size_t)ldb_i, ldc = (size_t)ldc_i;
    size_t ps = (size_t)T * 64;                 // part column stride (elements)
    const __nv_bfloat16* Ab = A + (size_t)blockIdx.y * 128 * lda;
    const __nv_bfloat16* Bb = B + (size_t)blockIdx.x * 128 * ldb;

    int ldrow = tid >> 3;       // 0..63
    int ldc8  = tid & 7;        // 16B chunk within 128B row

    auto issue = [&](uint32_t sst, int kt) {
        size_t kofs = (size_t)kt * 64 + ldc8 * 8;
        #pragma unroll
        for (int p = 0; p < NT; p++) {
            const __nv_bfloat16* ag = Ab + p * ps + kofs;
            uint32_t sp = sst + p * 16384u;
            #pragma unroll
            for (int i = 0; i < 2; i++) {
                int row = ldrow + i * 64;
                uint32_t ph = (uint32_t)(ldc8 ^ (row & 7));
                cp16(sp + row * 128 + ph * 16, ag + (size_t)row * lda);
            }
        }
        #pragma unroll
        for (int p = 0; p < NT; p++) {
            const __nv_bfloat16* bg = Bb + p * ps + kofs;
            uint32_t sp = sst + NT * 16384u + p * 16384u;
            #pragma unroll
            for (int i = 0; i < 2; i++) {
                int row = ldrow + i * 64;
                uint32_t ph = (uint32_t)(ldc8 ^ (row & 7));
                cp16(sp + row * 128 + ph * 16, bg + (size_t)row * ldb);
            }
        }
        CP_COMMIT();
    };

    int g  = lane >> 3, lr = lane & 7;
    int arow0 = warp_m * 32 + (g & 1) * 8 + lr;   // + mt*16, mt in 0..1
    int ac    = g >> 1;
    int brow0 = warp_n * 32 + (g >> 1) * 8 + lr;  // + np*16, np in 0..1
    int bc    = g & 1;

    issue(sbase, 0);
    issue(sbase + STAGE, 1);

    float acc[2][4][4] = {};

    for (int kt = 0; kt < T; kt++) {
        if (kt + 1 < T) { CP_WAIT1(); } else { CP_WAIT0(); }
        __syncthreads();
        uint32_t sst = sbase + (uint32_t)(kt & 1) * STAGE;

        #pragma unroll
        for (int ks = 0; ks < 4; ks++) {
            uint32_t afp[NT][2][4];
            uint32_t pha = (uint32_t)((2 * ks + ac) ^ (arow0 & 7));
            #pragma unroll
            for (int p = 0; p < NT; p++) {
                uint32_t sap = sst + p * 16384u;
                #pragma unroll
                for (int mt = 0; mt < 2; mt++) {
                    int row = arow0 + mt * 16;
                    LDSM4(afp[p][mt][0], afp[p][mt][1], afp[p][mt][2], afp[p][mt][3],
                          sap + row * 128 + pha * 16);
                }
            }
            uint32_t phb = (uint32_t)((2 * ks + bc) ^ (brow0 & 7));
            #pragma unroll
            for (int pb = 0; pb < NT; pb++) {
                uint32_t sbp = sst + NT * 16384u + pb * 16384u;
                uint32_t bf[4][2];
                #pragma unroll
                for (int np = 0; np < 2; np++) {
                    int row = brow0 + np * 16;
                    uint32_t r0, r1, r2, r3;
                    LDSM4(r0, r1, r2, r3, sbp + row * 128 + phb * 16);
                    bf[2*np][0] = r0; bf[2*np][1] = r1;
                    bf[2*np+1][0] = r2; bf[2*np+1][1] = r3;
                }
                #pragma unroll
                for (int pa = 0; pa < NT; pa++) {
                    if (pa + pb < NT) {
                        #pragma unroll
                        for (int mt = 0; mt < 2; mt++)
                            #pragma unroll
                            for (int nt = 0; nt < 4; nt++)
                                MMA16816(acc[mt][nt], afp[pa][mt], bf[nt]);
                    }
                }
            }
        }
        __syncthreads();
        if (kt + 2 < T)
            issue(sst, kt + 2);
    }

    int crow = blockIdx.y * 128 + warp_m * 32 + (lane >> 2);
    int ccol = blockIdx.x * 128 + warp_n * 32 + (lane & 3) * 2;
    #pragma unroll
    for (int mt = 0; mt < 2; mt++) {
        #pragma unroll
        for (int nt = 0; nt < 4; nt++) {
            float* p = C + (size_t)(crow + mt * 16) * ldc + ccol + nt * 8;
            p[0] = acc[mt][nt][0]; p[1] = acc[mt][nt][1];
            float* p2 = p + 8 * ldc;
            p2[0] = acc[mt][nt][2]; p2[1] = acc[mt][nt][3];
        }
    }
}

// ===================== causal flash attention: 128-row x 64-col tiles =====================
// smem (floats): qT[64][132] | kT[64][68] | vS[64][68] | pS[128][68]  = 103.4 KB
// Pointers pre-offset for batch; grid = (SS/128, HH). Writes AOp split-2 bf16 directly.
#define FLQ_OFF 0
#define FLK_OFF 8448
#define FLV_OFF 12800
#define FLP_OFF 17152
#define FL_FLOATS 25856
__global__ __launch_bounds__(256, 2)
void flash_fp32(const float* __restrict__ Qb, const float* __restrict__ Kb,
                const float* __restrict__ Vb, __nv_bfloat16* __restrict__ AOp)
{
    extern __shared__ float smf[];
    float* qT = smf + FLQ_OFF;   // [d][row], stride 132
    float* kT = smf + FLK_OFF;   // [d][col], stride 68
    float* vS = smf + FLV_OFF;   // [k][dh],  stride 68
    float* pS = smf + FLP_OFF;   // [row][k], stride 68

    int tid = threadIdx.x;
    int tx = tid & 15, ty = tid >> 4;
    int lane = tid & 31;
    unsigned gmask = 0xFFFFu << (lane & 16);   // 16-lane segment mask
    int qb = (int)gridDim.x - 1 - blockIdx.x;  // heavy CTAs first (0..15)
    int h = blockIdx.y;
    size_t base = (size_t)h * DH;

    const float scale = 0.125f;
    const float SKIP_MARGIN = 20.0f;
    // load Q tile (128 rows), scaled, transposed: qT[d][row]
    for (int i = tid; i < 128*16; i += 256) {
        int row = i >> 4, j = i & 15;
        float4 q = *(const float4*)(Qb + base + (size_t)(qb*128 + row)*DD + j*4);
        qT[(j*4+0)*132 + row] = q.x * scale;
        qT[(j*4+1)*132 + row] = q.y * scale;
        qT[(j*4+2)*132 + row] = q.z * scale;
        qT[(j*4+3)*132 + row] = q.w * scale;
    }

    u64t o2[8][2] = {};
    float m_i[8], l_i[8];
    #pragma unroll
    for (int i = 0; i < 8; i++) { m_i[i] = -3.0e38f; l_i[i] = 0.f; }

    int jb_max = 2*qb + 1;
    for (int jb = 0; jb <= jb_max; jb++) {
        __syncthreads();
        for (int i = tid; i < 64*16; i += 256) {
            int row = i >> 4, j = i & 15;
            float4 kv = *(const float4*)(Kb + base + (size_t)(jb*64 + row)*DD + j*4);
            kT[(j*4+0)*68 + row] = kv.x; kT[(j*4+1)*68 + row] = kv.y;
            kT[(j*4+2)*68 + row] = kv.z; kT[(j*4+3)*68 + row] = kv.w;
            float4 vv = *(const float4*)(Vb + base + (size_t)(jb*64 + row)*DD + j*4);
            *(float4*)&vS[row*68 + j*4] = vv;
        }
        __syncthreads();

        // scores: rank-1 over d; s2[8 rows][2 col-pairs]
        u64t s2[8][2] = {};
        #pragma unroll 8
        for (int d = 0; d < 64; d++) {
            const float* qr = &qT[d*132 + ty*8];
            float4 a0 = *(const float4*)qr;
            float4 a1 = *(const float4*)(qr + 4);
            ulonglong2 bb = *(const ulonglong2*)&kT[d*68 + tx*4];
            u64t ad[8];
            ad[0] = pack2(a0.x, a0.x); ad[1] = pack2(a0.y, a0.y);
            ad[2] = pack2(a0.z, a0.z); ad[3] = pack2(a0.w, a0.w);
            ad[4] = pack2(a1.x, a1.x); ad[5] = pack2(a1.y, a1.y);
            ad[6] = pack2(a1.z, a1.z); ad[7] = pack2(a1.w, a1.w);
            #pragma unroll
            for (int i = 0; i < 8; i++) {
                fma2(s2[i][0], ad[i], bb.x);
                fma2(s2[i][1], ad[i], bb.y);
            }
        }

        // per-row softmax + skip; store pS (row-major, conflict-free)
        int thread_active = 0;
        #pragma unroll
        for (int i = 0; i < 8; i++) {
            float s[4];
            unpack2(s2[i][0], s[0], s[1]);
            unpack2(s2[i][1], s[2], s[3]);
            if (jb >= 2*qb) {   // diagonal region of this 128-row block
                int grow = qb*128 + ty*8 + i;
                int gc0  = jb*64 + tx*4;
                #pragma unroll
                for (int j = 0; j < 4; j++)
                    if (gc0 + j > grow) s[j] = -1.0e30f;
            }
            float mt = fmaxf(fmaxf(s[0], s[1]), fmaxf(s[2], s[3]));
            #pragma unroll
            for (int off = 8; off > 0; off >>= 1)
                mt = fmaxf(mt, __shfl_xor_sync(gmask, mt, off, 16));
            float* pr = &pS[(ty*8 + i)*68 + tx*4];
            if (mt < m_i[i] - SKIP_MARGIN) {
                *(float4*)pr = make_float4(0.f, 0.f, 0.f, 0.f);
                continue;   // uniform across the 16-lane segment
            }
            thread_active = 1;
            float mn = fmaxf(m_i[i], mt);
            float alpha = __expf(m_i[i] - mn);
            m_i[i] = mn;
            float ls = 0.f;
            #pragma unroll
            for (int j = 0; j < 4; j++) {
                float p = __expf(s[j] - mn);
                s[j] = p;
                ls += p;
            }
            #pragma unroll
            for (int off = 8; off > 0; off >>= 1)
                ls += __shfl_xor_sync(gmask, ls, off, 16);
            l_i[i] = l_i[i] * alpha + ls;
            u64t al = pack2(alpha, alpha);
            mul2(o2[i][0], al);
            mul2(o2[i][1], al);
            *(float4*)pr = make_float4(s[0], s[1], s[2], s[3]);
        }

        int any = __syncthreads_or(thread_active);   // publishes pS
        if (!any) continue;

        if (thread_active) {
            // PV: thread tile 8 rows x 4 dh; p read as 4-wide broadcasts per row
            #pragma unroll 2
            for (int k4 = 0; k4 < 16; k4++) {
                float4 p4[8];
                #pragma unroll
                for (int i = 0; i < 8; i++)
                    p4[i] = *(const float4*)&pS[(ty*8 + i)*68 + k4*4];
                #pragma unroll
                for (int kk = 0; kk < 4; kk++) {
                    int k = k4*4 + kk;
                    ulonglong2 bv = *(const ulonglong2*)&vS[k*68 + tx*4];
                    #pragma unroll
                    for (int i = 0; i < 8; i++) {
                        float pv = (kk == 0) ? p4[i].x : (kk == 1) ? p4[i].y
                                 : (kk == 2) ? p4[i].z : p4[i].w;
                        u64t a = pack2(pv, pv);
                        fma2(o2[i][0], a, bv.x);
                        fma2(o2[i][1], a, bv.y);
                    }
                }
            }
        }
    }

    // epilogue: normalize, split-2 to bf16, write AOp {h | m} directly
    #pragma unroll
    for (int i = 0; i < 8; i++) {
        float inv = 1.0f / l_i[i];
        int s_idx = qb*128 + ty*8 + i;
        float v0, v1, v2, v3;
        unpack2(o2[i][0], v0, v1);
        unpack2(o2[i][1], v2, v3);
        v0 *= inv; v1 *= inv; v2 *= inv; v3 *= inv;
        __nv_bfloat16 ph[4], pm[4];
        split2f(v0, ph[0], pm[0]); split2f(v1, ph[1], pm[1]);
        split2f(v2, ph[2], pm[2]); split2f(v3, ph[3], pm[3]);
        __nv_bfloat16* o = AOp + (size_t)s_idx * 2048 + h * DH + tx * 4;
        *(uint2*)o          = *(const uint2*)ph;
        *(uint2*)(o + 1024) = *(const uint2*)pm;
    }
}

// ===================== launch =====================
extern "C" void kernel_launch(void* const* d_in, const int* in_sizes, int n_in,
                              void* d_out, int out_size)
{
    const float* x     = (const float*)d_in[0];
    const float* wfqkQ = (const float*)d_in[1];
    const float* wfqkK = (const float*)d_in[2];
    const float* wfv   = (const float*)d_in[3];
    const float* wrqkQ = (const float*)d_in[4];
    const float* wrqkK = (const float*)d_in[5];
    const float* wrv   = (const float*)d_in[6];
    const float* f_qk  = (const float*)d_in[7];
    const float* f_v   = (const float*)d_in[8];
    const float* r_qk  = (const float*)d_in[9];
    const float* r_v   = (const float*)d_in[10];
    const float* W_O   = (const float*)d_in[11];
    float* out = (float*)d_out;

    __nv_bfloat16 *Xp, *Fp, *Fvp, *HWp, *HWv, *Rp, *Rvp, *WOp, *AOp;
    float *P, *P2, *hq, *hk, *hv, *QK, *V;
    cudaGetSymbolAddress((void**)&Xp,  g_Xp);
    cudaGetSymbolAddress((void**)&Fp,  g_Fp);
    cudaGetSymbolAddress((void**)&Fvp, g_Fvp);
    cudaGetSymbolAddress((void**)&HWp, g_HWp);
    cudaGetSymbolAddress((void**)&HWv, g_HWv);
    cudaGetSymbolAddress((void**)&Rp,  g_Rp);
    cudaGetSymbolAddress((void**)&Rvp, g_Rvp);
    cudaGetSymbolAddress((void**)&WOp, g_WOp);
    cudaGetSymbolAddress((void**)&AOp, g_AOp);
    cudaGetSymbolAddress((void**)&P,  g_P);
    cudaGetSymbolAddress((void**)&P2, g_P2);
    cudaGetSymbolAddress((void**)&hq, g_hq);
    cudaGetSymbolAddress((void**)&hk, g_hk);
    cudaGetSymbolAddress((void**)&hv, g_hv);
    cudaGetSymbolAddress((void**)&QK, g_QK);
    cudaGetSymbolAddress((void**)&V,  g_V);

    int smem3 = 2 * 3 * 32768;   // 196608
    int smem2 = 2 * 2 * 32768;   // 131072
    int fl_smem = FL_FLOATS * (int)sizeof(float);   // 103424
    cudaFuncSetAttribute(tgemm_p<3>, cudaFuncAttributeMaxDynamicSharedMemorySize, smem3);
    cudaFuncSetAttribute(tgemm_p<2>, cudaFuncAttributeMaxDynamicSharedMemorySize, smem2);
    cudaFuncSetAttribute(flash_fp32, cudaFuncAttributeMaxDynamicSharedMemorySize, fl_smem);

    // fork/join resources (created once, OUTSIDE graph capture)
    static cudaStream_t s2 = nullptr, s3 = nullptr;
    static cudaEvent_t evX = nullptr, evV = nullptr, evR0 = nullptr, evO0 = nullptr;
    if (s2 == nullptr) {
        cudaStreamCreateWithFlags(&s2, cudaStreamNonBlocking);
        cudaStreamCreateWithFlags(&s3, cudaStreamNonBlocking);
        cudaEventCreateWithFlags(&evX,  cudaEventDisableTiming);
        cudaEventCreateWithFlags(&evV,  cudaEventDisableTiming);
        cudaEventCreateWithFlags(&evR0, cudaEventDisableTiming);
        cudaEventCreateWithFlags(&evO0, cudaEventDisableTiming);
    }

    // buffer geometry: HWp rows [Qb0 | Kb0 | Qb1 | Kb1] (2048 rows each, stride 6144)
    //                  QK rows  [Qb0 | Kb0 | Qb1 | Kb1] (2048 rows each, stride 1024)
    const size_t HWB = (size_t)2048 * 6144;
    const size_t QKB = (size_t)2048 * DD;

    // ===== stream 0: shared prefix + QK chain =====
    conv_x3 <<<(BS*DD)/256, 256>>>(x, Xp);
    cudaEventRecord(evX, 0);                 // Xp ready -> fork V chain
    cudaStreamWaitEvent(s2, evX, 0);

    conv_f3 <<<(NR*DD)/256, 256>>>(f_qk, Fp);
    conv_r3 <<<(DD*NR)/256, 256>>>(r_qk, Rp);
    tgemm_p<3><<<dim3(NR/128, BS/128), 512, smem3>>>(Xp, Fp, P, 3072, 3072, NR, 16);
    reduce_h2<<<(BS*RR)/256, 256>>>(P, wfqkQ, wfqkK, hq, hk);
    build_hw3<<<(2048*NR)/256, 256>>>(hq,           wrqkQ,           HWp + 0*HWB);   // Q b0
    build_hw3<<<(2048*NR)/256, 256>>>(hk,           wrqkK,           HWp + 1*HWB);   // K b0
    build_hw3<<<(2048*NR)/256, 256>>>(hq + 2048*RR, wrqkQ + 2048*NN, HWp + 2*HWB);   // Q b1
    build_hw3<<<(2048*NR)/256, 256>>>(hk + 2048*RR, wrqkK + 2048*NN, HWp + 3*HWB);   // K b1
    // restore batch 0
    tgemm_p<3><<<dim3(DD/128, 32), 512, smem3>>>(HWp, Rp, QK, 6144, 6144, DD, 32);
    cudaEventRecord(evR0, 0);
    // restore batch 1 (concurrent with flash_b0 on s3)
    tgemm_p<3><<<dim3(DD/128, 32), 512, smem3>>>(HWp + 2*HWB, Rp, QK + 2*QKB, 6144, 6144, DD, 32);

    // ===== stream s2: V chain =====
    conv_f2 <<<(NR*DD)/256, 256, 0, s2>>>(f_v,  Fvp);
    conv_r2 <<<(DD*NR)/256, 256, 0, s2>>>(r_v,  Rvp);
    conv_wo2<<<(DD*DD)/256, 256, 0, s2>>>(W_O,  WOp);
    tgemm_p<2><<<dim3(NR/128, BS/128), 512, smem2, s2>>>(Xp, Fvp, P2, 3072, 2048, NR, 16);
    reduce_h1<<<(BS*RR)/256, 256, 0, s2>>>(P2, wfv, hv);
    build_hw2<<<(BS*NR)/256, 256, 0, s2>>>(hv, wrv, HWv);
    tgemm_p<2><<<dim3(DD/128, BS/128), 512, smem2, s2>>>(HWv, Rvp, V, 4096, 4096, DD, 32);
    cudaEventRecord(evV, s2);

    // ===== stream s3: flash_b0 + out-proj_b0 =====
    cudaStreamWaitEvent(s3, evR0, 0);
    cudaStreamWaitEvent(s3, evV, 0);
    flash_fp32<<<dim3(SS/128, HH), 256, fl_smem, s3>>>(QK, QK + QKB, V, AOp);
    tgemm_p<2><<<dim3(DD/128, SS/128), 512, smem2, s3>>>(AOp, WOp, out, 2048, 2048, DD, 16);
    cudaEventRecord(evO0, s3);

    // ===== stream 0: flash_b1 + out-proj_b1, then join s3 =====
    cudaStreamWaitEvent(0, evV, 0);
    flash_fp32<<<dim3(SS/128, HH), 256, fl_smem>>>(QK + 2*QKB, QK + 3*QKB,
                                                   V + (size_t)SS*DD, AOp + (size_t)SS*2048);
    tgemm_p<2><<<dim3(DD/128, SS/128), 512, smem2>>>(AOp + (size_t)SS*2048, WOp,
                                                     out + (size_t)SS*DD, 2048, 2048, DD, 16);
    cudaStreamWaitEvent(0, evO0, 0);   // join s3
}

// round 16
// speedup vs baseline: 1.0376x; 1.0376x over previous
#include <cuda_runtime.h>
#include <cuda_bf16.h>
#include <stdint.h>
#include <math.h>

// Problem constants
#define BB 2
#define SS 2048
#define DD 1024
#define RR 64
#define HH 16
#define DH 64
#define NN 32
#define BS (BB*SS)        // 4096
#define NR (NN*RR)        // 2048

// ===================== PTX helpers (compute_103-safe) =====================
__device__ __forceinline__ uint32_t smem_u32(const void* p) {
    uint32_t a;
    asm("{ .reg .u64 t; cvta.to.shared.u64 t, %1; cvt.u32.u64 %0, t; }" : "=r"(a) : "l"(p));
    return a;
}
__device__ __forceinline__ void cp16(uint32_t saddr, const void* g) {
    asm volatile("cp.async.cg.shared.global [%0], [%1], 16;" :: "r"(saddr), "l"(g) : "memory");
}
#define CP_COMMIT() asm volatile("cp.async.commit_group;" ::: "memory")
#define CP_WAIT1()  asm volatile("cp.async.wait_group 1;" ::: "memory")
#define CP_WAIT0()  asm volatile("cp.async.wait_group 0;" ::: "memory")

#define LDSM4(r0, r1, r2, r3, addr) \
    asm volatile("ldmatrix.sync.aligned.m8n8.x4.shared.b16 {%0,%1,%2,%3}, [%4];" \
        : "=r"(r0), "=r"(r1), "=r"(r2), "=r"(r3) : "r"(addr))

#define MMA16816(d, a, b) \
    asm volatile("mma.sync.aligned.m16n8k16.row.col.f32.bf16.bf16.f32 " \
        "{%0,%1,%2,%3}, {%4,%5,%6,%7}, {%8,%9}, {%0,%1,%2,%3};" \
        : "+f"((d)[0]), "+f"((d)[1]), "+f"((d)[2]), "+f"((d)[3]) \
        : "r"((a)[0]), "r"((a)[1]), "r"((a)[2]), "r"((a)[3]), "r"((b)[0]), "r"((b)[1]))

// packed fp32 (Blackwell f32x2)
typedef unsigned long long u64t;
__device__ __forceinline__ u64t pack2(float lo, float hi) {
    u64t r; asm("mov.b64 %0, {%1,%2};" : "=l"(r) : "f"(lo), "f"(hi)); return r;
}
__device__ __forceinline__ void unpack2(u64t v, float& lo, float& hi) {
    asm("mov.b64 {%0,%1}, %2;" : "=f"(lo), "=f"(hi) : "l"(v));
}
__device__ __forceinline__ void fma2(u64t& d, u64t a, u64t b) {
    asm("fma.rn.f32x2 %0, %1, %2, %0;" : "+l"(d) : "l"(a), "l"(b));
}
__device__ __forceinline__ void mul2(u64t& d, u64t a) {
    asm("mul.rn.f32x2 %0, %0, %1;" : "+l"(d) : "l"(a));
}

// ===================== scratch (device globals) — COMPACT part layout =====================
__device__ __align__(256) __nv_bfloat16 g_Xp  [(size_t)BS * 3072];      // X  {h,m,l}
__device__ __align__(256) __nv_bfloat16 g_Fp  [(size_t)NR * 3072];      // f_qk^T {h,m,l}
__device__ __align__(256) __nv_bfloat16 g_Fvp [(size_t)NR * 2048];      // f_v^T {h,m}
__device__ __align__(256) __nv_bfloat16 g_HWp [(size_t)2 * BS * 6144];  // [Qb0|Kb0|Qb1|Kb1] {h,m,l}
__device__ __align__(256) __nv_bfloat16 g_HWv [(size_t)BS * 4096];      // HW v {h,m}
__device__ __align__(256) __nv_bfloat16 g_Rp  [(size_t)DD * 6144];      // r_qk^T {h,m,l}
__device__ __align__(256) __nv_bfloat16 g_Rvp [(size_t)DD * 4096];      // r_v^T {h,m}
__device__ __align__(256) __nv_bfloat16 g_WOp [(size_t)DD * 2048];      // W_O {h,m}
__device__ __align__(256) __nv_bfloat16 g_AOp [(size_t)BS * 2048];      // AO {h,m} (written by flash)
__device__ float g_P  [(size_t)BS * NR];      // proj-qk output
__device__ float g_P2 [(size_t)BS * NR];      // proj-v output
__device__ float g_hq [BS * RR];
__device__ float g_hk [BS * RR];
__device__ float g_hv [BS * RR];
__device__ float g_QK [(size_t)2 * BS * DD];  // [Qb0 | Kb0 | Qb1 | Kb1], 2048x1024 each
__device__ float g_V  [(size_t)BS * DD];

// ===================== split helpers =====================
__device__ __forceinline__ void split3f(float x, __nv_bfloat16& h, __nv_bfloat16& m, __nv_bfloat16& l) {
    h = __float2bfloat16_rn(x);
    float r = x - __bfloat162float(h);
    m = __float2bfloat16_rn(r);
    r -= __bfloat162float(m);
    l = __float2bfloat16_rn(r);
}
__device__ __forceinline__ void split2f(float x, __nv_bfloat16& h, __nv_bfloat16& m) {
    h = __float2bfloat16_rn(x);
    m = __float2bfloat16_rn(x - __bfloat162float(h));
}

__global__ void conv_x3(const float* __restrict__ in, __nv_bfloat16* __restrict__ out) {
    size_t gid = (size_t)blockIdx.x * 256 + threadIdx.x;  // BS*DD
    size_t row = gid >> 10; int col = (int)(gid & 1023);
    __nv_bfloat16 h, m, l; split3f(in[gid], h, m, l);
    __nv_bfloat16* o = out + row * 3072 + col;
    o[0] = h; o[1024] = m; o[2048] = l;
}

__global__ void conv_f3(const float* __restrict__ f, __nv_bfloat16* __restrict__ out) {
    size_t gid = (size_t)blockIdx.x * 256 + threadIdx.x;   // NR*DD
    int nr = (int)(gid >> 10), d = (int)(gid & 1023);
    int n = nr >> 6, r = nr & 63;
    __nv_bfloat16 h, m, l; split3f(f[((size_t)n << 16) + (d << 6) + r], h, m, l);
    __nv_bfloat16* o = out + (size_t)nr * 3072 + d;
    o[0] = h; o[1024] = m; o[2048] = l;
}
__global__ void conv_f2(const float* __restrict__ f, __nv_bfloat16* __restrict__ out) {
    size_t gid = (size_t)blockIdx.x * 256 + threadIdx.x;
    int nr = (int)(gid >> 10), d = (int)(gid & 1023);
    int n = nr >> 6, r = nr & 63;
    __nv_bfloat16 h, m, l; split3f(f[((size_t)n << 16) + (d << 6) + r], h, m, l);
    __nv_bfloat16* o = out + (size_t)nr * 2048 + d;
    o[0] = h; o[1024] = m;
}

__global__ void conv_r3(const float* __restrict__ rk, __nv_bfloat16* __restrict__ out) {
    size_t gid = (size_t)blockIdx.x * 256 + threadIdx.x;   // DD*NR
    int d = (int)(gid >> 11), nr = (int)(gid & 2047);
    int n = nr >> 6, r = nr & 63;
    __nv_bfloat16 h, m, l; split3f(rk[((size_t)n << 16) + (r << 10) + d], h, m, l);
    __nv_bfloat16* o = out + (size_t)d * 6144 + nr;
    o[0] = h; o[2048] = m; o[4096] = l;
}
__global__ void conv_r2(const float* __restrict__ rv, __nv_bfloat16* __restrict__ out) {
    size_t gid = (size_t)blockIdx.x * 256 + threadIdx.x;
    int d = (int)(gid >> 11), nr = (int)(gid & 2047);
    int n = nr >> 6, r = nr & 63;
    __nv_bfloat16 h, m, l; split3f(rv[((size_t)n << 16) + (r << 10) + d], h, m, l);
    __nv_bfloat16* o = out + (size_t)d * 4096 + nr;
    o[0] = h; o[2048] = m;
}

__global__ void conv_wo2(const float* __restrict__ w, __nv_bfloat16* __restrict__ out) {
    size_t gid = (size_t)blockIdx.x * 256 + threadIdx.x;  // DD*DD
    size_t row = gid >> 10; int col = (int)(gid & 1023);
    __nv_bfloat16 h, m, l; split3f(w[gid], h, m, l);
    __nv_bfloat16* o = out + row * 2048 + col;
    o[0] = h; o[1024] = m;
}

// HW {h,m,l} over 2048 rows (one batch, one of q/k): out[row][3*2048]
__global__ void build_hw3(const float* __restrict__ hbuf, const float* __restrict__ w,
                          __nv_bfloat16* __restrict__ out) {
    size_t gid = (size_t)blockIdx.x * 256 + threadIdx.x;   // 2048*NR
    int bs = (int)(gid >> 11), nr = (int)(gid & 2047);
    int n = nr >> 6, r = nr & 63;
    float p = hbuf[bs * RR + r] * w[bs * NN + n];
    __nv_bfloat16 h, m, l; split3f(p, h, m, l);
    __nv_bfloat16* o = out + (size_t)bs * 6144 + nr;
    o[0] = h; o[2048] = m; o[4096] = l;
}
__global__ void build_hw2(const float* __restrict__ hbuf, const float* __restrict__ w,
                          __nv_bfloat16* __restrict__ out) {
    size_t gid = (size_t)blockIdx.x * 256 + threadIdx.x;   // BS*NR
    int bs = (int)(gid >> 11), nr = (int)(gid & 2047);
    int n = nr >> 6, r = nr & 63;
    float p = hbuf[bs * RR + r] * w[bs * NN + n];
    __nv_bfloat16 h, m, l; split3f(p, h, m, l);
    __nv_bfloat16* o = out + (size_t)bs * 4096 + nr;
    o[0] = h; o[2048] = m;
}

// ===================== h reductions (P fp32) =====================
__global__ void reduce_h2(const float* __restrict__ P,
                          const float* __restrict__ wQ, const float* __restrict__ wK,
                          float* __restrict__ hq, float* __restrict__ hk) {
    int gid = blockIdx.x * 256 + threadIdx.x;   // BS*RR
    int bs = gid >> 6, r = gid & 63;
    const float* Pr = P + (size_t)bs * NR + r;
    const float* wq = wQ + bs * NN;
    const float* wk = wK + bs * NN;
    float aq = 0.f, ak = 0.f;
    #pragma unroll
    for (int n = 0; n < NN; n++) {
        float p = Pr[n * RR];
        aq += wq[n] * p;
        ak += wk[n] * p;
    }
    hq[gid] = aq; hk[gid] = ak;
}
__global__ void reduce_h1(const float* __restrict__ P, const float* __restrict__ w,
                          float* __restrict__ h) {
    int gid = blockIdx.x * 256 + threadIdx.x;
    int bs = gid >> 6, r = gid & 63;
    const float* Pr = P + (size_t)bs * NR + r;
    const float* ww = w + bs * NN;
    float a = 0.f;
    #pragma unroll
    for (int n = 0; n < NN; n++) a += ww[n] * Pr[n * RR];
    h[gid] = a;
}

// ===================== fused multi-part bf16 mma.sync GEMM (512 thr) =====================
template<int NT>
__global__ __launch_bounds__(512, 1)
void tgemm_p(const __nv_bfloat16* __restrict__ A, const __nv_bfloat16* __restrict__ B,
             float* __restrict__ C, int lda_i, int ldb_i, int ldc_i, int T)
{
    extern __shared__ char sm[];
    const uint32_t STAGE = NT * 32768u;
    uint32_t sbase = smem_u32(sm);
    int tid = threadIdx.x, wid = tid >> 5, lane = tid & 31;
    int warp_m = wid & 3, warp_n = wid >> 2;    // 4 x 4
    size_t lda = (size_t)lda_i, ldb = (size_t)ldb_i, ldc = (size_t)ldc_i;
    size_t ps = (size_t)T * 64;                 // part column stride (elements)
    const __nv_bfloat16* Ab = A + (size_t)blockIdx.y * 128 * lda;
    const __nv_bfloat16* Bb = B + (size_t)blockIdx.x * 128 * ldb;

    int ldrow = tid >> 3;       // 0..63
    int ldc8  = tid & 7;        // 16B chunk within 128B row

    auto issue = [&](uint32_t sst, int kt) {
        size_t kofs = (size_t)kt * 64 + ldc8 * 8;
        #pragma unroll
        for (int p = 0; p < NT; p++) {
            const __nv_bfloat16* ag = Ab + p * ps + kofs;
            uint32_t sp = sst + p * 16384u;
            #pragma unroll
            for (int i = 0; i < 2; i++) {
                int row = ldrow + i * 64;
                uint32_t ph = (uint32_t)(ldc8 ^ (row & 7));
                cp16(sp + row * 128 + ph * 16, ag + (size_t)row * lda);
            }
        }
        #pragma unroll
        for (int p = 0; p < NT; p++) {
            const __nv_bfloat16* bg = Bb + p * ps + kofs;
            uint32_t sp = sst + NT * 16384u + p * 16384u;
            #pragma unroll
            for (int i = 0; i < 2; i++) {
                int row = ldrow + i * 64;
                uint32_t ph = (uint32_t)(ldc8 ^ (row & 7));
                cp16(sp + row * 128 + ph * 16, bg + (size_t)row * ldb);
            }
        }
        CP_COMMIT();
    };

    int g  = lane >> 3, lr = lane & 7;
    int arow0 = warp_m * 32 + (g & 1) * 8 + lr;   // + mt*16, mt in 0..1
    int ac    = g >> 1;
    int brow0 = warp_n * 32 + (g >> 1) * 8 + lr;  // + np*16, np in 0..1
    int bc    = g & 1;

    issue(sbase, 0);
    issue(sbase + STAGE, 1);

    float acc[2][4][4] = {};

    for (int kt = 0; kt < T; kt++) {
        if (kt + 1 < T) { CP_WAIT1(); } else { CP_WAIT0(); }
        __syncthreads();
        uint32_t sst = sbase + (uint32_t)(kt & 1) * STAGE;

        #pragma unroll
        for (int ks = 0; ks < 4; ks++) {
            uint32_t afp[NT][2][4];
            uint32_t pha = (uint32_t)((2 * ks + ac) ^ (arow0 & 7));
            #pragma unroll
            for (int p = 0; p < NT; p++) {
                uint32_t sap = sst + p * 16384u;
                #pragma unroll
                for (int mt = 0; mt < 2; mt++) {
                    int row = arow0 + mt * 16;
                    LDSM4(afp[p][mt][0], afp[p][mt][1], afp[p][mt][2], afp[p][mt][3],
                          sap + row * 128 + pha * 16);
                }
            }
            uint32_t phb = (uint32_t)((2 * ks + bc) ^ (brow0 & 7));
            #pragma unroll
            for (int pb = 0; pb < NT; pb++) {
                uint32_t sbp = sst + NT * 16384u + pb * 16384u;
                uint32_t bf[4][2];
                #pragma unroll
                for (int np = 0; np < 2; np++) {
                    int row = brow0 + np * 16;
                    uint32_t r0, r1, r2, r3;
                    LDSM4(r0, r1, r2, r3, sbp + row * 128 + phb * 16);
                    bf[2*np][0] = r0; bf[2*np][1] = r1;
                    bf[2*np+1][0] = r2; bf[2*np+1][1] = r3;
                }
                #pragma unroll
                for (int pa = 0; pa < NT; pa++) {
                    if (pa + pb < NT) {
                        #pragma unroll
                        for (int mt = 0; mt < 2; mt++)
                            #pragma unroll
                            for (int nt = 0; nt < 4; nt++)
                                MMA16816(acc[mt][nt], afp[pa][mt], bf[nt]);
                    }
                }
            }
        }
        __syncthreads();
        if (kt + 2 < T)
            issue(sst, kt + 2);
    }

    int crow = blockIdx.y * 128 + warp_m * 32 + (lane >> 2);
    int ccol = blockIdx.x * 128 + warp_n * 32 + (lane & 3) * 2;
    #pragma unroll
    for (int mt = 0; mt < 2; mt++) {
        #pragma unroll
        for (int nt = 0; nt < 4; nt++) {
            float* p = C + (size_t)(crow + mt * 16) * ldc + ccol + nt * 8;
            p[0] = acc[mt][nt][0]; p[1] = acc[mt][nt][1];
            float* p2 = p + 8 * ldc;
            p2[0] = acc[mt][nt][2]; p2[1] = acc[mt][nt][3];
        }
    }
}

// ===================== causal flash attention (R13-proven: 64x64, f32x2, skip) =====================
// Pointers pre-offset for batch; grid = (SS/64, HH). Writes AOp split-2 bf16 directly.
__global__ __launch_bounds__(256)
void flash_fp32(const float* __restrict__ Qb, const float* __restrict__ Kb,
                const float* __restrict__ Vb, __nv_bfloat16* __restrict__ AOp)
{
    extern __shared__ float smf[];
    float (*qT)[68] = (float(*)[68])(smf);
    float (*kT)[68] = (float(*)[68])(smf + 64*68);
    float (*vS)[68] = (float(*)[68])(smf + 2*64*68);

    int tid = threadIdx.x;
    int tx = tid & 15, ty = tid >> 4;
    int lane = tid & 31;
    unsigned gmask = 0xFFFFu << (lane & 16);   // 16-lane segment mask
    int qb = (int)gridDim.x - 1 - blockIdx.x;  // heavy CTAs first
    int h = blockIdx.y;
    size_t base = (size_t)h * DH;

    const float scale = 0.125f;
    const float SKIP_MARGIN = 20.0f;
    for (int i = tid; i < 64*16; i += 256) {
        int row = i >> 4, j = i & 15;
        float4 q = *(const float4*)(Qb + base + (size_t)(qb*64 + row)*DD + j*4);
        qT[j*4+0][row] = q.x * scale;
        qT[j*4+1][row] = q.y * scale;
        qT[j*4+2][row] = q.z * scale;
        qT[j*4+3][row] = q.w * scale;
    }

    u64t o2[4][2] = {};
    float m_i[4], l_i[4];
    #pragma unroll
    for (int i = 0; i < 4; i++) { m_i[i] = -3.0e38f; l_i[i] = 0.f; }

    for (int jb = 0; jb <= qb; jb++) {
        __syncthreads();
        for (int i = tid; i < 64*16; i += 256) {
            int row = i >> 4, j = i & 15;
            float4 kv = *(const float4*)(Kb + base + (size_t)(jb*64 + row)*DD + j*4);
            kT[j*4+0][row] = kv.x; kT[j*4+1][row] = kv.y;
            kT[j*4+2][row] = kv.z; kT[j*4+3][row] = kv.w;
            float4 vv = *(const float4*)(Vb + base + (size_t)(jb*64 + row)*DD + j*4);
            *(float4*)&vS[row][j*4] = vv;
        }
        __syncthreads();

        u64t s2[4][2] = {};
        #pragma unroll 16
        for (int d = 0; d < 64; d++) {
            float4 a = *(const float4*)&qT[d][ty*4];
            ulonglong2 bb = *(const ulonglong2*)&kT[d][tx*4];
            u64t a0 = pack2(a.x, a.x), a1 = pack2(a.y, a.y);
            u64t a2 = pack2(a.z, a.z), a3 = pack2(a.w, a.w);
            fma2(s2[0][0], a0, bb.x); fma2(s2[0][1], a0, bb.y);
            fma2(s2[1][0], a1, bb.x); fma2(s2[1][1], a1, bb.y);
            fma2(s2[2][0], a2, bb.x); fma2(s2[2][1], a2, bb.y);
            fma2(s2[3][0], a3, bb.x); fma2(s2[3][1], a3, bb.y);
        }
        float s[4][4];
        #pragma unroll
        for (int i = 0; i < 4; i++) {
            unpack2(s2[i][0], s[i][0], s[i][1]);
            unpack2(s2[i][1], s[i][2], s[i][3]);
        }
        if (jb == qb) {
            #pragma unroll
            for (int i = 0; i < 4; i++)
                #pragma unroll
                for (int j = 0; j < 4; j++)
                    if (tx*4 + j > ty*4 + i) s[i][j] = -1.0e30f;
        }

        int thread_active = 0;
        #pragma unroll
        for (int i = 0; i < 4; i++) {
            float mt = fmaxf(fmaxf(s[i][0], s[i][1]), fmaxf(s[i][2], s[i][3]));
            #pragma unroll
            for (int off = 8; off > 0; off >>= 1)
                mt = fmaxf(mt, __shfl_xor_sync(gmask, mt, off, 16));
            if (mt < m_i[i] - SKIP_MARGIN) {
                s[i][0] = 0.f; s[i][1] = 0.f; s[i][2] = 0.f; s[i][3] = 0.f;
                continue;   // uniform across the 16-lane segment
            }
            thread_active = 1;
            float mn = fmaxf(m_i[i], mt);
            float alpha = __expf(m_i[i] - mn);
            m_i[i] = mn;
            float ls = 0.f;
            #pragma unroll
            for (int j = 0; j < 4; j++) {
                float p = __expf(s[i][j] - mn);
                s[i][j] = p;
                ls += p;
            }
            #pragma unroll
            for (int off = 8; off > 0; off >>= 1)
                ls += __shfl_xor_sync(gmask, ls, off, 16);
            l_i[i] = l_i[i] * alpha + ls;
            u64t al = pack2(alpha, alpha);
            mul2(o2[i][0], al);
            mul2(o2[i][1], al);
        }

        int any = __syncthreads_or(thread_active);
        if (!any) continue;

        if (thread_active) {
            #pragma unroll
            for (int i = 0; i < 4; i++)
                #pragma unroll
                for (int j = 0; j < 4; j++)
                    kT[tx*4 + j][ty*4 + i] = s[i][j];
        }
        __syncthreads();

        if (thread_active) {
            #pragma unroll 16
            for (int k = 0; k < 64; k++) {
                float4 a = *(const float4*)&kT[k][ty*4];
                ulonglong2 bv = *(const ulonglong2*)&vS[k][tx*4];
                u64t a0 = pack2(a.x, a.x), a1 = pack2(a.y, a.y);
                u64t a2 = pack2(a.z, a.z), a3 = pack2(a.w, a.w);
                fma2(o2[0][0], a0, bv.x); fma2(o2[0][1], a0, bv.y);
                fma2(o2[1][0], a1, bv.x); fma2(o2[1][1], a1, bv.y);
                fma2(o2[2][0], a2, bv.x); fma2(o2[2][1], a2, bv.y);
                fma2(o2[3][0], a3, bv.x); fma2(o2[3][1], a3, bv.y);
            }
        }
    }

    #pragma unroll
    for (int i = 0; i < 4; i++) {
        float inv = 1.0f / l_i[i];
        int s_idx = qb*64 + ty*4 + i;
        float v0, v1, v2, v3;
        unpack2(o2[i][0], v0, v1);
        unpack2(o2[i][1], v2, v3);
        v0 *= inv; v1 *= inv; v2 *= inv; v3 *= inv;
        __nv_bfloat16 ph[4], pm[4];
        split2f(v0, ph[0], pm[0]); split2f(v1, ph[1], pm[1]);
        split2f(v2, ph[2], pm[2]); split2f(v3, ph[3], pm[3]);
        __nv_bfloat16* o = AOp + (size_t)s_idx * 2048 + h * DH + tx * 4;
        *(uint2*)o          = *(const uint2*)ph;
        *(uint2*)(o + 1024) = *(const uint2*)pm;
    }
}

// ===================== launch =====================
extern "C" void kernel_launch(void* const* d_in, const int* in_sizes, int n_in,
                              void* d_out, int out_size)
{
    const float* x     = (const float*)d_in[0];
    const float* wfqkQ = (const float*)d_in[1];
    const float* wfqkK = (const float*)d_in[2];
    const float* wfv   = (const float*)d_in[3];
    const float* wrqkQ = (const float*)d_in[4];
    const float* wrqkK = (const float*)d_in[5];
    const float* wrv   = (const float*)d_in[6];
    const float* f_qk  = (const float*)d_in[7];
    const float* f_v   = (const float*)d_in[8];
    const float* r_qk  = (const float*)d_in[9];
    const float* r_v   = (const float*)d_in[10];
    const float* W_O   = (const float*)d_in[11];
    float* out = (float*)d_out;

    __nv_bfloat16 *Xp, *Fp, *Fvp, *HWp, *HWv, *Rp, *Rvp, *WOp, *AOp;
    float *P, *P2, *hq, *hk, *hv, *QK, *V;
    cudaGetSymbolAddress((void**)&Xp,  g_Xp);
    cudaGetSymbolAddress((void**)&Fp,  g_Fp);
    cudaGetSymbolAddress((void**)&Fvp, g_Fvp);
    cudaGetSymbolAddress((void**)&HWp, g_HWp);
    cudaGetSymbolAddress((void**)&HWv, g_HWv);
    cudaGetSymbolAddress((void**)&Rp,  g_Rp);
    cudaGetSymbolAddress((void**)&Rvp, g_Rvp);
    cudaGetSymbolAddress((void**)&WOp, g_WOp);
    cudaGetSymbolAddress((void**)&AOp, g_AOp);
    cudaGetSymbolAddress((void**)&P,  g_P);
    cudaGetSymbolAddress((void**)&P2, g_P2);
    cudaGetSymbolAddress((void**)&hq, g_hq);
    cudaGetSymbolAddress((void**)&hk, g_hk);
    cudaGetSymbolAddress((void**)&hv, g_hv);
    cudaGetSymbolAddress((void**)&QK, g_QK);
    cudaGetSymbolAddress((void**)&V,  g_V);

    int smem3 = 2 * 3 * 32768;   // 196608
    int smem2 = 2 * 2 * 32768;   // 131072
    int fl_smem = 3 * 64 * 68 * (int)sizeof(float);   // 52224
    cudaFuncSetAttribute(tgemm_p<3>, cudaFuncAttributeMaxDynamicSharedMemorySize, smem3);
    cudaFuncSetAttribute(tgemm_p<2>, cudaFuncAttributeMaxDynamicSharedMemorySize, smem2);
    cudaFuncSetAttribute(flash_fp32, cudaFuncAttributeMaxDynamicSharedMemorySize, fl_smem);

    // fork/join resources (created once, OUTSIDE graph capture)
    static cudaStream_t s2 = nullptr, s3 = nullptr;
    static cudaEvent_t evX = nullptr, evV = nullptr, evR0 = nullptr, evO0 = nullptr;
    static cudaEvent_t evH = nullptr, evB1 = nullptr;
    if (s2 == nullptr) {
        cudaStreamCreateWithFlags(&s2, cudaStreamNonBlocking);
        cudaStreamCreateWithFlags(&s3, cudaStreamNonBlocking);
        cudaEventCreateWithFlags(&evX,  cudaEventDisableTiming);
        cudaEventCreateWithFlags(&evV,  cudaEventDisableTiming);
        cudaEventCreateWithFlags(&evR0, cudaEventDisableTiming);
        cudaEventCreateWithFlags(&evO0, cudaEventDisableTiming);
        cudaEventCreateWithFlags(&evH,  cudaEventDisableTiming);
        cudaEventCreateWithFlags(&evB1, cudaEventDisableTiming);
    }

    // buffer geometry: HWp rows [Qb0 | Kb0 | Qb1 | Kb1] (2048 rows each, stride 6144)
    //                  QK rows  [Qb0 | Kb0 | Qb1 | Kb1] (2048 rows each, stride 1024)
    const size_t HWB = (size_t)2048 * 6144;
    const size_t QKB = (size_t)2048 * DD;

    // ===== stream 0: shared prefix + batch-0 QK chain =====
    conv_x3 <<<(BS*DD)/256, 256>>>(x, Xp);
    cudaEventRecord(evX, 0);                 // Xp ready -> fork V chain
    cudaStreamWaitEvent(s2, evX, 0);

    conv_f3 <<<(NR*DD)/256, 256>>>(f_qk, Fp);
    conv_r3 <<<(DD*NR)/256, 256>>>(r_qk, Rp);
    tgemm_p<3><<<dim3(NR/128, BS/128), 512, smem3>>>(Xp, Fp, P, 3072, 3072, NR, 16);
    reduce_h2<<<(BS*RR)/256, 256>>>(P, wfqkQ, wfqkK, hq, hk);
    cudaEventRecord(evH, 0);                 // hq/hk ready -> batch-1 builds on s2
    // batch-0 builds only, then restore_b0 starts earlier
    build_hw3<<<(2048*NR)/256, 256>>>(hq, wrqkQ, HWp + 0*HWB);   // Q b0
    build_hw3<<<(2048*NR)/256, 256>>>(hk, wrqkK, HWp + 1*HWB);   // K b0
    tgemm_p<3><<<dim3(DD/128, 32), 512, smem3>>>(HWp, Rp, QK, 6144, 6144, DD, 32);
    cudaEventRecord(evR0, 0);

    // ===== stream s2: V chain + batch-1 builds (enqueued BEFORE waits on its events) =====
    conv_f2 <<<(NR*DD)/256, 256, 0, s2>>>(f_v,  Fvp);
    conv_r2 <<<(DD*NR)/256, 256, 0, s2>>>(r_v,  Rvp);
    conv_wo2<<<(DD*DD)/256, 256, 0, s2>>>(W_O,  WOp);
    tgemm_p<2><<<dim3(NR/128, BS/128), 512, smem2, s2>>>(Xp, Fvp, P2, 3072, 2048, NR, 16);
    reduce_h1<<<(BS*RR)/256, 256, 0, s2>>>(P2, wfv, hv);
    build_hw2<<<(BS*NR)/256, 256, 0, s2>>>(hv, wrv, HWv);
    tgemm_p<2><<<dim3(DD/128, BS/128), 512, smem2, s2>>>(HWv, Rvp, V, 4096, 4096, DD, 32);
    cudaEventRecord(evV, s2);
    cudaStreamWaitEvent(s2, evH, 0);
    build_hw3<<<(2048*NR)/256, 256, 0, s2>>>(hq + 2048*RR, wrqkQ + 2048*NN, HWp + 2*HWB);  // Q b1
    build_hw3<<<(2048*NR)/256, 256, 0, s2>>>(hk + 2048*RR, wrqkK + 2048*NN, HWp + 3*HWB);  // K b1
    cudaEventRecord(evB1, s2);

    // ===== stream 0: restore batch 1 (after evB1 recorded in program order) =====
    cudaStreamWaitEvent(0, evB1, 0);
    tgemm_p<3><<<dim3(DD/128, 32), 512, smem3>>>(HWp + 2*HWB, Rp, QK + 2*QKB, 6144, 6144, DD, 32);

    // ===== stream s3: flash_b0 + out-proj_b0 (overlaps restore_b1) =====
    cudaStreamWaitEvent(s3, evR0, 0);
    cudaStreamWaitEvent(s3, evV, 0);
    flash_fp32<<<dim3(SS/64, HH), 256, fl_smem, s3>>>(QK, QK + QKB, V, AOp);
    tgemm_p<2><<<dim3(DD/128, SS/128), 512, smem2, s3>>>(AOp, WOp, out, 2048, 2048, DD, 16);
    cudaEventRecord(evO0, s3);

    // ===== stream 0: flash_b1 + out-proj_b1, then join s3 =====
    cudaStreamWaitEvent(0, evV, 0);
    flash_fp32<<<dim3(SS/64, HH), 256, fl_smem>>>(QK + 2*QKB, QK + 3*QKB,
                                                  V + (size_t)SS*DD, AOp + (size_t)SS*2048);
    tgemm_p<2><<<dim3(DD/128, SS/128), 512, smem2>>>(AOp + (size_t)SS*2048, WOp,
                                                     out + (size_t)SS*DD, 2048, 2048, DD, 16);
    cudaStreamWaitEvent(0, evO0, 0);   // join s3
}